// round 10
// baseline (speedup 1.0000x reference)
#include <cuda_runtime.h>
#include <math.h>

// Sampler: Gumbel-keys relaxed top-k. khot = sum_{t=1..k} softmax(att_g_t),
// att_g_{t+1} = att_g_t + log(max(1 - onehot_t, eps)).
// One CTA per row (B=128 rows, n=1024), all state in registers. Latency-chain
// bound -> minimize barrier round-trips, shfl pressure, and issue slots:
//  (1) fixed softmax shift M0 (logits monotone non-increasing), computed once.
//  (2) unnormalized numerators: oh = e/S; acc += oh; e <- e*(1-oh).
//  (3) DEPTH-3 STEP FUSION via moments (S,P2,P3,P4):
//        S2 = S - P2/S;  Q2 = P2 - (2*P3 - P4/S)/S;  S3 = S2 - Q2/S2
//      gated on participation P2 < 0.9*S^2 (block-uniform). One-shot error:
//      every sync re-reduces exact sums from the e registers.
//  (4) 128 threads / 4 warps (1 per SMSP): minimal shfl/MIO pressure.
//  (5) PACKED f32x2 math (Blackwell FFMA2) for moments + update rounds:
//      halves elementwise issue count; butterfly stays scalar (4 moments).

#define NTHREADS 128
#define NWARPS   (NTHREADS / 32)       // 4
#define NNODES   1024
#define EPT      (NNODES / NTHREADS)   // 8
#define NPAIR    (EPT / 2)             // 4 packed f32x2 pairs
#define EPS_F    1.1754943508222875e-38f  // np.finfo(float32).tiny
#define LOG2E    1.4426950408889634f

typedef unsigned long long u64;

__device__ __forceinline__ float ex2_approx(float x) {
    float r; asm("ex2.approx.f32 %0, %1;" : "=f"(r) : "f"(x)); return r;
}
__device__ __forceinline__ float rcp_approx(float x) {
    float r; asm("rcp.approx.f32 %0, %1;" : "=f"(r) : "f"(x)); return r;
}
__device__ __forceinline__ u64 pk(float lo, float hi) {
    u64 r; asm("mov.b64 %0, {%1, %2};" : "=l"(r) : "f"(lo), "f"(hi)); return r;
}
__device__ __forceinline__ void upk(float& lo, float& hi, u64 v) {
    asm("mov.b64 {%0, %1}, %2;" : "=f"(lo), "=f"(hi) : "l"(v));
}
__device__ __forceinline__ u64 fma2(u64 a, u64 b, u64 c) {
    u64 r; asm("fma.rn.f32x2 %0, %1, %2, %3;" : "=l"(r) : "l"(a), "l"(b), "l"(c));
    return r;
}
__device__ __forceinline__ u64 mul2(u64 a, u64 b) {
    u64 r; asm("mul.rn.f32x2 %0, %1, %2;" : "=l"(r) : "l"(a), "l"(b)); return r;
}
__device__ __forceinline__ u64 add2(u64 a, u64 b) {
    u64 r; asm("add.rn.f32x2 %0, %1, %2;" : "=l"(r) : "l"(a), "l"(b)); return r;
}
__device__ __forceinline__ u64 neg2(u64 a) {           // flip both sign bits
    return a ^ 0x8000000080000000ULL;
}
__device__ __forceinline__ float4 add4(float4 a, float4 b) {
    return make_float4(a.x + b.x, a.y + b.y, a.z + b.z, a.w + b.w);
}

__global__ __launch_bounds__(NTHREADS, 1)
void sampler_topk_kernel(const float* __restrict__ att,
                         const float* __restrict__ uni,
                         const int*  __restrict__ kptr,
                         float* __restrict__ out)
{
    // per-warp moment vectors (S,P2,P3,P4), double-buffered: single barrier
    // per sync is race-free (write buf(t+2) after bar(t+1); reads of buf(t)
    // between bar(t) and bar(t+1)).
    __shared__ __align__(16) float4 sm4[2][NWARPS];
    __shared__ __align__(16) float  sm_m[NWARPS];

    const int row  = blockIdx.x;
    const int tid  = threadIdx.x;
    const int lane = tid & 31;
    const int warp = tid >> 5;
    const int k    = *kptr;

    const float* __restrict__ arow = att + row * NNODES;
    const float* __restrict__ urow = uni + row * NNODES;
    float*       __restrict__ orow = out + row * NNODES;

    u64 e[NPAIR], acc[NPAIR];

    // Gumbel init in log2 domain: b = (att - log(-log(u+eps))) * log2(e)
    {
        float b[EPT];
        float m = -3.402823466e38f;
        #pragma unroll
        for (int j = 0; j < EPT; ++j) {
            const int idx = tid + j * NTHREADS;      // coalesced
            float u = urow[idx];
            b[j] = (arow[idx] - logf(-logf(u + EPS_F))) * LOG2E;
            m = fmaxf(m, b[j]);
        }
        // one-time block max M0 (valid shift forever: logits only decrease)
        #pragma unroll
        for (int o = 16; o > 0; o >>= 1)
            m = fmaxf(m, __shfl_xor_sync(0xffffffffu, m, o));
        if (lane == 0) sm_m[warp] = m;
        __syncthreads();
        float4 mv = *(const float4*)&sm_m[0];
        float M = fmaxf(fmaxf(mv.x, mv.y), fmaxf(mv.z, mv.w));
        #pragma unroll
        for (int p = 0; p < NPAIR; ++p) {
            e[p]   = pk(ex2_approx(b[2*p] - M), ex2_approx(b[2*p+1] - M));
            acc[p] = 0ULL;
        }
    }

    int steps_left = k;
    int it = 0;
    while (steps_left > 0) {
        // ---- packed local moments, then horizontal add ----
        u64 sP = 0, p2P = 0, p3P = 0, p4P = 0;
        #pragma unroll
        for (int p = 0; p < NPAIR; ++p) {
            u64 x  = e[p];
            u64 x2 = mul2(x, x);
            sP  = add2(sP, x);
            p2P = fma2(x,  x,  p2P);
            p3P = fma2(x2, x,  p3P);
            p4P = fma2(x2, x2, p4P);
        }
        float s, p2, p3, p4, hl, hh;
        upk(hl, hh, sP);  s  = hl + hh;
        upk(hl, hh, p2P); p2 = hl + hh;
        upk(hl, hh, p3P); p3 = hl + hh;
        upk(hl, hh, p4P); p4 = hl + hh;
        // ---- 4-wide interleaved warp butterflies (1 warp per SMSP) ----
        #pragma unroll
        for (int o = 16; o > 0; o >>= 1) {
            s  += __shfl_xor_sync(0xffffffffu, s,  o);
            p2 += __shfl_xor_sync(0xffffffffu, p2, o);
            p3 += __shfl_xor_sync(0xffffffffu, p3, o);
            p4 += __shfl_xor_sync(0xffffffffu, p4, o);
        }
        const int buf = it & 1;
        if (lane == 0) sm4[buf][warp] = make_float4(s, p2, p3, p4);
        __syncthreads();
        const float4* sv = &sm4[buf][0];
        float4 t = add4(add4(sv[0], sv[1]), add4(sv[2], sv[3]));
        const float S = t.x, P2 = t.y, P3 = t.z, P4 = t.w;

        // ---- round A: scale = 1/S ----
        float rA = rcp_approx(S);
        u64 rA2 = pk(rA, rA);
        #pragma unroll
        for (int p = 0; p < NPAIR; ++p) {
            u64 oh = mul2(e[p], rA2);
            acc[p] = add2(acc[p], oh);
            e[p]   = fma2(neg2(oh), e[p], e[p]);     // e*(1-oh)
        }
        steps_left -= 1;

        if (steps_left > 0) {
            // ---- round B: S2 = S - P2/S ----
            float S2 = __fmaf_rn(-P2, rA, S);
            S2 = fmaxf(S2, S * 1e-6f);
            float rB = rcp_approx(S2);
            u64 rB2 = pk(rB, rB);
            #pragma unroll
            for (int p = 0; p < NPAIR; ++p) {
                u64 oh = mul2(e[p], rB2);
                acc[p] = add2(acc[p], oh);
                e[p]   = fma2(neg2(oh), e[p], e[p]);
            }
            steps_left -= 1;

            // ---- round C (gated): S3 = S2 - Q2/S2 ----
            if (steps_left > 0 && P2 < 0.9f * (S * S)) {
                float u  = __fmaf_rn(-P4, rA, 2.0f * P3);  // 2*P3 - P4/S
                float Q2 = __fmaf_rn(-u, rA, P2);          // P2 - u/S
                Q2 = fmaxf(Q2, 0.0f);
                float S3 = __fmaf_rn(-Q2, rB, S2);
                S3 = fmaxf(S3, S2 * 1e-6f);
                float rC = rcp_approx(S3);
                u64 rC2 = pk(rC, rC);
                #pragma unroll
                for (int p = 0; p < NPAIR; ++p) {
                    u64 oh = mul2(e[p], rC2);
                    acc[p] = add2(acc[p], oh);
                    e[p]   = fma2(neg2(oh), e[p], e[p]);
                }
                steps_left -= 1;
            }
        }
        ++it;
    }

    #pragma unroll
    for (int p = 0; p < NPAIR; ++p) {
        float lo, hi;
        upk(lo, hi, acc[p]);
        orow[tid + (2*p)     * NTHREADS] = lo;
        orow[tid + (2*p + 1) * NTHREADS] = hi;
    }
}

extern "C" void kernel_launch(void* const* d_in, const int* in_sizes, int n_in,
                              void* d_out, int out_size)
{
    const float* att = (const float*)d_in[0];
    const float* uni = (const float*)d_in[1];
    const int*   kp  = (const int*)d_in[2];
    float* out = (float*)d_out;

    const int B = in_sizes[0] / NNODES;   // 128
    sampler_topk_kernel<<<B, NTHREADS>>>(att, uni, kp, out);
}

// round 11
// speedup vs baseline: 1.1515x; 1.1515x over previous
#include <cuda_runtime.h>
#include <math.h>

// Sampler: Gumbel-keys relaxed top-k. khot = sum_{t=1..k} softmax(att_g_t),
// att_g_{t+1} = att_g_t + log(max(1 - onehot_t, eps)).
// One CTA per row (B=128 rows, n=1024), all state in registers. Latency-chain
// bound -> minimize barrier round-trips and shuffle-throughput pressure:
//  (1) fixed softmax shift M0 (logits monotone non-increasing), computed once.
//  (2) unnormalized numerators: oh = e/S; acc += oh; e <- e*(1-oh).
//  (3) DEPTH-3 STEP FUSION via moments (S,P2,P3,P4):
//        S2 = S - P2/S;  Q2 = P2 - (2*P3 - P4/S)/S;  S3 = S2 - Q2/S2
//      gated on participation P2 < 0.9*S^2 (block-uniform). One-shot error:
//      every sync re-reduces exact sums from the e registers.
//  (4) 128 threads / 4 warps (1 per SMSP).
//  (5) TRANSPOSE BUTTERFLY: reduce the 4 moments across the warp in 6 shfls
//      (2 exchange-halving levels + 3 plain levels) instead of 20 — SHFL/MIO
//      throughput was the dominant reduction cost (R6/R7/R8 marginal ~20cy/shfl).

#define NTHREADS 128
#define NWARPS   (NTHREADS / 32)       // 4
#define NNODES   1024
#define EPT      (NNODES / NTHREADS)   // 8
#define EPS_F    1.1754943508222875e-38f  // np.finfo(float32).tiny
#define LOG2E    1.4426950408889634f

__device__ __forceinline__ float ex2_approx(float x) {
    float r; asm("ex2.approx.f32 %0, %1;" : "=f"(r) : "f"(x)); return r;
}
__device__ __forceinline__ float rcp_approx(float x) {
    float r; asm("rcp.approx.f32 %0, %1;" : "=f"(r) : "f"(x)); return r;
}
__device__ __forceinline__ float4 add4(float4 a, float4 b) {
    return make_float4(a.x + b.x, a.y + b.y, a.z + b.z, a.w + b.w);
}

__global__ __launch_bounds__(NTHREADS, 1)
void sampler_topk_kernel(const float* __restrict__ att,
                         const float* __restrict__ uni,
                         const int*  __restrict__ kptr,
                         float* __restrict__ out)
{
    // per-warp moment vectors (S,P2,P3,P4), double-buffered: single barrier
    // per sync is race-free (write buf(t+2) after bar(t+1); reads of buf(t)
    // between bar(t) and bar(t+1)).
    __shared__ __align__(16) float4 sm4[2][NWARPS];
    __shared__ __align__(16) float  sm_m[NWARPS];

    const int row  = blockIdx.x;
    const int tid  = threadIdx.x;
    const int lane = tid & 31;
    const int warp = tid >> 5;
    const int k    = *kptr;

    const float* __restrict__ arow = att + row * NNODES;
    const float* __restrict__ urow = uni + row * NNODES;
    float*       __restrict__ orow = out + row * NNODES;

    float e[EPT], acc[EPT];

    // Gumbel init in log2 domain: b = (att - log(-log(u+eps))) * log2(e)
    {
        float b[EPT];
        float m = -3.402823466e38f;
        #pragma unroll
        for (int j = 0; j < EPT; ++j) {
            const int idx = tid + j * NTHREADS;      // coalesced
            float u = urow[idx];
            b[j] = (arow[idx] - logf(-logf(u + EPS_F))) * LOG2E;
            m = fmaxf(m, b[j]);
            acc[j] = 0.0f;
        }
        // one-time block max M0 (valid shift forever: logits only decrease)
        #pragma unroll
        for (int o = 16; o > 0; o >>= 1)
            m = fmaxf(m, __shfl_xor_sync(0xffffffffu, m, o));
        if (lane == 0) sm_m[warp] = m;
        __syncthreads();
        float4 mv = *(const float4*)&sm_m[0];
        float M = fmaxf(fmaxf(mv.x, mv.y), fmaxf(mv.z, mv.w));
        #pragma unroll
        for (int j = 0; j < EPT; ++j)
            e[j] = ex2_approx(b[j] - M);             // unnormalized numerators
    }

    const bool b0 = (lane & 1) != 0;
    const bool b1 = (lane & 2) != 0;
    // smem write index for lanes 0..3 (moment permutation from the transpose):
    // lane&3: 0->S(0), 1->P3(2), 2->P2(1), 3->P4(3)
    const int widx = ((lane & 1) << 1) | ((lane >> 1) & 1);

    int steps_left = k;
    int it = 0;
    while (steps_left > 0) {
        // ---- local moments: s, p2, p3, p4 (FMA-fused) ----
        float s = 0.f, p2 = 0.f, p3 = 0.f, p4 = 0.f;
        #pragma unroll
        for (int j = 0; j < EPT; ++j) {
            float x  = e[j];
            float x2 = x * x;
            s  += x;
            p2 = __fmaf_rn(x,  x,  p2);
            p3 = __fmaf_rn(x2, x,  p3);
            p4 = __fmaf_rn(x2, x2, p4);
        }
        // ---- transpose butterfly: 4 values reduced in 6 shfls ----
        // L1 (o=1): lanes bit0=0 keep (s,p2) pair-sums; bit0=1 keep (p3,p4)
        float send0 = b0 ? s  : p3;
        float send1 = b0 ? p2 : p4;
        float r0 = __shfl_xor_sync(0xffffffffu, send0, 1);
        float r1 = __shfl_xor_sync(0xffffffffu, send1, 1);
        float a0 = (b0 ? p3 : s)  + r0;
        float a1 = (b0 ? p4 : p2) + r1;
        // L2 (o=2): bit1=0 keep a0's value; bit1=1 keep a1's value
        float send2 = b1 ? a0 : a1;
        float r2 = __shfl_xor_sync(0xffffffffu, send2, 2);
        float c = (b1 ? a1 : a0) + r2;
        // L3-5 (o=4,8,16): plain butterfly on the single carried value
        c += __shfl_xor_sync(0xffffffffu, c, 4);
        c += __shfl_xor_sync(0xffffffffu, c, 8);
        c += __shfl_xor_sync(0xffffffffu, c, 16);
        // lane l (l<4) holds warp total of moment perm(l); scatter to float4
        const int buf = it & 1;
        if (lane < 4) ((float*)&sm4[buf][warp])[widx] = c;
        __syncthreads();
        const float4* sv = &sm4[buf][0];
        float4 t = add4(add4(sv[0], sv[1]), add4(sv[2], sv[3]));
        const float S = t.x, P2 = t.y, P3 = t.z, P4 = t.w;

        // ---- round A: scale = 1/S ----
        float rA = rcp_approx(S);
        #pragma unroll
        for (int j = 0; j < EPT; ++j) {
            float oh = e[j] * rA;
            acc[j] += oh;
            e[j] = __fmaf_rn(-oh, e[j], e[j]);       // e*(1-oh)
        }
        steps_left -= 1;

        if (steps_left > 0) {
            // ---- round B: S2 = S - P2/S ----
            float S2 = __fmaf_rn(-P2, rA, S);
            S2 = fmaxf(S2, S * 1e-6f);
            float rB = rcp_approx(S2);
            #pragma unroll
            for (int j = 0; j < EPT; ++j) {
                float oh = e[j] * rB;
                acc[j] += oh;
                e[j] = __fmaf_rn(-oh, e[j], e[j]);
            }
            steps_left -= 1;

            // ---- round C (gated): S3 = S2 - Q2/S2 ----
            if (steps_left > 0 && P2 < 0.9f * (S * S)) {
                float u  = __fmaf_rn(-P4, rA, 2.0f * P3);  // 2*P3 - P4/S
                float Q2 = __fmaf_rn(-u, rA, P2);          // P2 - u/S
                Q2 = fmaxf(Q2, 0.0f);
                float S3 = __fmaf_rn(-Q2, rB, S2);
                S3 = fmaxf(S3, S2 * 1e-6f);
                float rC = rcp_approx(S3);
                #pragma unroll
                for (int j = 0; j < EPT; ++j) {
                    float oh = e[j] * rC;
                    acc[j] += oh;
                    e[j] = __fmaf_rn(-oh, e[j], e[j]);
                }
                steps_left -= 1;
            }
        }
        ++it;
    }

    #pragma unroll
    for (int j = 0; j < EPT; ++j)
        orow[tid + j * NTHREADS] = acc[j];
}

extern "C" void kernel_launch(void* const* d_in, const int* in_sizes, int n_in,
                              void* d_out, int out_size)
{
    const float* att = (const float*)d_in[0];
    const float* uni = (const float*)d_in[1];
    const int*   kp  = (const int*)d_in[2];
    float* out = (float*)d_out;

    const int B = in_sizes[0] / NNODES;   // 128
    sampler_topk_kernel<<<B, NTHREADS>>>(att, uni, kp, out);
}

// round 12
// speedup vs baseline: 1.2985x; 1.1276x over previous
#include <cuda_runtime.h>
#include <math.h>

// Sampler: Gumbel-keys relaxed top-k. khot = sum_{t=1..k} softmax(att_g_t),
// att_g_{t+1} = att_g_t + log(max(1 - onehot_t, eps)).
// One CTA per row (B=128 rows, n=1024), all state in registers. Latency-chain
// bound -> minimize barrier round-trips, shuffle pressure, and BRANCH overhead:
//  (1) fixed softmax shift M0 (logits monotone non-increasing), computed once.
//  (2) unnormalized numerators: oh = e/S; acc += oh; e <- e*(1-oh).
//  (3) DEPTH-3 STEP FUSION via moments (S,P2,P3,P4):
//        S2 = S - P2/S;  Q2 = P2 - (2*P3 - P4/S)/S;  S3 = S2 - Q2/S2
//      round C is BRANCHLESS: rC is zeroed by SELP when the participation
//      gate (P2 < 0.98*S^2) fails -> exact no-op, no BSSY/BSYNC in the loop.
//  (4) 128 threads / 4 warps (1 per SMSP); 6-shfl transpose butterfly.
//  (5) e^2 precomputed in the barrier-wait shadow -> round A is 2 instr/elem.
//  (6) main loop is branch-minimal (uniform trip); <=2 leftover steps in tail.

#define NTHREADS 128
#define NWARPS   (NTHREADS / 32)       // 4
#define NNODES   1024
#define EPT      (NNODES / NTHREADS)   // 8
#define EPS_F    1.1754943508222875e-38f  // np.finfo(float32).tiny
#define LOG2E    1.4426950408889634f

__device__ __forceinline__ float ex2_approx(float x) {
    float r; asm("ex2.approx.f32 %0, %1;" : "=f"(r) : "f"(x)); return r;
}
__device__ __forceinline__ float rcp_approx(float x) {
    float r; asm("rcp.approx.f32 %0, %1;" : "=f"(r) : "f"(x)); return r;
}
__device__ __forceinline__ float4 add4(float4 a, float4 b) {
    return make_float4(a.x + b.x, a.y + b.y, a.z + b.z, a.w + b.w);
}

__global__ __launch_bounds__(NTHREADS, 1)
void sampler_topk_kernel(const float* __restrict__ att,
                         const float* __restrict__ uni,
                         const int*  __restrict__ kptr,
                         float* __restrict__ out)
{
    // per-warp moment vectors (S,P2,P3,P4), double-buffered: single barrier
    // per sync is race-free (write buf(t+2) after bar(t+1); reads of buf(t)
    // between bar(t) and bar(t+1)).
    __shared__ __align__(16) float4 sm4[2][NWARPS];
    __shared__ __align__(16) float  sm_m[NWARPS];

    const int row  = blockIdx.x;
    const int tid  = threadIdx.x;
    const int lane = tid & 31;
    const int warp = tid >> 5;
    const int k    = *kptr;

    const float* __restrict__ arow = att + row * NNODES;
    const float* __restrict__ urow = uni + row * NNODES;
    float*       __restrict__ orow = out + row * NNODES;

    float e[EPT], acc[EPT];

    // Gumbel init in log2 domain: b = (att - log(-log(u+eps))) * log2(e)
    {
        float b[EPT];
        float m = -3.402823466e38f;
        #pragma unroll
        for (int j = 0; j < EPT; ++j) {
            const int idx = tid + j * NTHREADS;      // coalesced
            float u = urow[idx];
            b[j] = (arow[idx] - logf(-logf(u + EPS_F))) * LOG2E;
            m = fmaxf(m, b[j]);
            acc[j] = 0.0f;
        }
        // one-time block max M0 (valid shift forever: logits only decrease)
        #pragma unroll
        for (int o = 16; o > 0; o >>= 1)
            m = fmaxf(m, __shfl_xor_sync(0xffffffffu, m, o));
        if (lane == 0) sm_m[warp] = m;
        __syncthreads();
        float4 mv = *(const float4*)&sm_m[0];
        float M = fmaxf(fmaxf(mv.x, mv.y), fmaxf(mv.z, mv.w));
        #pragma unroll
        for (int j = 0; j < EPT; ++j)
            e[j] = ex2_approx(b[j] - M);             // unnormalized numerators
    }

    const bool b0 = (lane & 1) != 0;
    const bool b1 = (lane & 2) != 0;
    // smem write index for lanes 0..3 (moment permutation of the transpose):
    // lane&3: 0->S(0), 1->P3(2), 2->P2(1), 3->P4(3)
    const int widx = ((lane & 1) << 1) | ((lane >> 1) & 1);

    int steps = 0;
    int it = 0;
    while (steps <= k - 3) {
        // ---- local moments: s, p2, p3, p4 (FMA-fused) ----
        float s = 0.f, p2 = 0.f, p3 = 0.f, p4 = 0.f;
        #pragma unroll
        for (int j = 0; j < EPT; ++j) {
            float x  = e[j];
            float x2 = x * x;
            s  += x;
            p2 = __fmaf_rn(x,  x,  p2);
            p3 = __fmaf_rn(x2, x,  p3);
            p4 = __fmaf_rn(x2, x2, p4);
        }
        // ---- transpose butterfly: 4 values reduced in 6 shfls ----
        float send0 = b0 ? s  : p3;
        float send1 = b0 ? p2 : p4;
        float r0 = __shfl_xor_sync(0xffffffffu, send0, 1);
        float r1 = __shfl_xor_sync(0xffffffffu, send1, 1);
        float a0 = (b0 ? p3 : s)  + r0;
        float a1 = (b0 ? p4 : p2) + r1;
        float send2 = b1 ? a0 : a1;
        float r2 = __shfl_xor_sync(0xffffffffu, send2, 2);
        float c = (b1 ? a1 : a0) + r2;
        c += __shfl_xor_sync(0xffffffffu, c, 4);
        c += __shfl_xor_sync(0xffffffffu, c, 8);
        c += __shfl_xor_sync(0xffffffffu, c, 16);
        const int buf = it & 1;
        if (lane < 4) ((float*)&sm4[buf][warp])[widx] = c;
        // ---- shadow work while the barrier drains: e^2 for round A ----
        float e2[EPT];
        #pragma unroll
        for (int j = 0; j < EPT; ++j) e2[j] = e[j] * e[j];
        __syncthreads();
        const float4* sv = &sm4[buf][0];
        float4 t = add4(add4(sv[0], sv[1]), add4(sv[2], sv[3]));
        const float S = t.x, P2 = t.y, P3 = t.z, P4 = t.w;

        // ---- round A: 2 instr/elem (e^2 precomputed) ----
        float rA = rcp_approx(S);
        #pragma unroll
        for (int j = 0; j < EPT; ++j) {
            acc[j] = __fmaf_rn(e[j], rA, acc[j]);
            e[j]   = __fmaf_rn(-e2[j], rA, e[j]);    // e - e^2/S
        }
        // ---- round B: S2 = S - P2/S ----
        float S2 = __fmaf_rn(-P2, rA, S);
        S2 = fmaxf(S2, S * 1e-6f);
        float rB = rcp_approx(S2);
        #pragma unroll
        for (int j = 0; j < EPT; ++j) {
            float oh = e[j] * rB;
            acc[j] += oh;
            e[j] = __fmaf_rn(-oh, e[j], e[j]);
        }
        // ---- round C (branchless gate): S3 = S2 - Q2/S2 ----
        float u  = __fmaf_rn(-P4, rA, 2.0f * P3);    // 2*P3 - P4/S
        float Q2 = __fmaf_rn(-u, rA, P2);            // P2 - u/S
        Q2 = fminf(fmaxf(Q2, 0.0f), P2);             // 0 <= Q2 <= P2
        float S3 = __fmaf_rn(-Q2, rB, S2);
        S3 = fmaxf(S3, S2 * 1e-6f);
        const bool g = P2 < 0.98f * (S * S);
        float rC = g ? rcp_approx(S3) : 0.0f;        // rC=0 -> exact no-op
        #pragma unroll
        for (int j = 0; j < EPT; ++j) {
            float oh = e[j] * rC;
            acc[j] += oh;
            e[j] = __fmaf_rn(-oh, e[j], e[j]);
        }
        steps += g ? 3 : 2;
        ++it;
    }

    // ---- tail: 0..2 single steps (sum-only reduction) ----
    while (steps < k) {
        float s = 0.f;
        #pragma unroll
        for (int j = 0; j < EPT; ++j) s += e[j];
        #pragma unroll
        for (int o = 16; o > 0; o >>= 1)
            s += __shfl_xor_sync(0xffffffffu, s, o);
        __syncthreads();                  // protect sm_m reuse across iters
        if (lane == 0) sm_m[warp] = s;
        __syncthreads();
        float4 sv = *(const float4*)&sm_m[0];
        float S = (sv.x + sv.y) + (sv.z + sv.w);
        float r = rcp_approx(S);
        #pragma unroll
        for (int j = 0; j < EPT; ++j) {
            float oh = e[j] * r;
            acc[j] += oh;
            e[j] = __fmaf_rn(-oh, e[j], e[j]);
        }
        steps += 1;
    }

    #pragma unroll
    for (int j = 0; j < EPT; ++j)
        orow[tid + j * NTHREADS] = acc[j];
}

extern "C" void kernel_launch(void* const* d_in, const int* in_sizes, int n_in,
                              void* d_out, int out_size)
{
    const float* att = (const float*)d_in[0];
    const float* uni = (const float*)d_in[1];
    const int*   kp  = (const int*)d_in[2];
    float* out = (float*)d_out;

    const int B = in_sizes[0] / NNODES;   // 128
    sampler_topk_kernel<<<B, NTHREADS>>>(att, uni, kp, out);
}